// round 14
// baseline (speedup 1.0000x reference)
#include <cuda_runtime.h>
#include <cuda_fp16.h>
#include <cstdint>
#include <cstddef>

// ---------------------------------------------------------------------------
// Problem constants
// ---------------------------------------------------------------------------
#define BATCH 4
#define SEQ   2048
#define DIM   1024

// GEMM tiling: 128x128 CTA tile, 4 warps of 64x64, K chunks of 64 fp16.
#define KC     64
#define LDT    72                       // padded row stride in fp16 (144 B)
#define TILE_P (128 * LDT * 2)          // 18432 B per tile
#define STG_B  (2 * TILE_P)             // 36864 B (A + B)
#define NS     3                        // pipeline stages
#define SMEM_B (NS * STG_B)             // 110592 B -> 2 CTAs/SM
#define GT     128                      // threads per CTA (4 warps)

#define SM_SCALE 0.03125f               // 1/sqrt(1024)

// Work-queue items (topological order)
#define N_PX   256                      // x -> fp16 (4 items per 128-row blk)
#define N_PW   1024                     // weight transpose (64x64 tiles)
#define N_QKV  1536                     // 24 x 64
#define N_SC   544                      // 136 tri-tiles x 4 batches
#define N_PV   512                      // 8 x 16 x 4
#define N_WO   512                      // 8 x 64
#define B_PW   (N_PX)
#define B_QKV  (N_PX + N_PW)
#define B_SC   (B_QKV + N_QKV)
#define B_PV   (B_SC + N_SC)
#define B_WO   (B_PV + N_PV)
#define N_ALL  (B_WO + N_WO)            // 4384

#define NWORKERS 304                    // >= 2 CTAs/SM x 152 SMs (any size safe)

// Counter layout
#define C_QK   0                        // [0:64)    qk row-blocks, target 16
#define C_V    64                       // [64:128)  v row-blocks, target 8
#define C_SC   128                      // [128:192) scores rows, target r+1
#define C_PV   192                      // [192:256) pv rows, target 8
#define C_X    256                      // [256:320) x row-blocks, target 4
#define C_WQ   320                      // [320:344) qkv W^T col-blocks, 32
#define C_WO   344                      // [344:352) Wo  W^T col-blocks, 32
#define Q_HEAD 384                      // work-queue head
#define N_CNT  512

// ---------------------------------------------------------------------------
// PTX helpers (base sm_103 ISA: cp.async, ldmatrix, mma.sync)
// ---------------------------------------------------------------------------
__device__ __forceinline__ uint32_t smem_u32(const void* p) {
    uint32_t a;
    asm("{ .reg .u64 t; cvta.to.shared.u64 t, %1; cvt.u32.u64 %0, t; }"
        : "=r"(a) : "l"(p));
    return a;
}
__device__ __forceinline__ void cpa16(uint32_t dst, const void* src) {
    asm volatile("cp.async.cg.shared.global [%0], [%1], 16;"
                 :: "r"(dst), "l"(src));
}
__device__ __forceinline__ void cpa_commit() {
    asm volatile("cp.async.commit_group;");
}
__device__ __forceinline__ void ldm_x4(uint32_t* r, uint32_t addr) {
    asm volatile("ldmatrix.sync.aligned.m8n8.x4.shared.b16 {%0,%1,%2,%3}, [%4];"
                 : "=r"(r[0]), "=r"(r[1]), "=r"(r[2]), "=r"(r[3]) : "r"(addr));
}
__device__ __forceinline__ void mma16816(float* d, const uint32_t* a,
                                         uint32_t b0, uint32_t b1) {
    asm volatile(
        "mma.sync.aligned.m16n8k16.row.col.f32.f16.f16.f32 "
        "{%0,%1,%2,%3}, {%4,%5,%6,%7}, {%8,%9}, {%0,%1,%2,%3};"
        : "+f"(d[0]), "+f"(d[1]), "+f"(d[2]), "+f"(d[3])
        : "r"(a[0]), "r"(a[1]), "r"(a[2]), "r"(a[3]), "r"(b0), "r"(b1));
}
__device__ __forceinline__ uint32_t pack2h(float a, float b) {
    __half ha = __float2half_rn(a), hb = __float2half_rn(b);
    return (uint32_t)__half_as_ushort(ha) | ((uint32_t)__half_as_ushort(hb) << 16);
}

// ---------------------------------------------------------------------------
// Device scratch + dependency counters
// ---------------------------------------------------------------------------
#define RXD ((size_t)BATCH * SEQ * DIM)
#define RSS ((size_t)BATCH * SEQ * SEQ)
__device__ __half g_xh[RXD];                             // x fp16
__device__ __half g_wqkvth[3 * DIM * DIM];               // W_{q|k|v}^T fp16
__device__ __half g_woth[DIM * DIM];                     // Wo^T fp16
__device__ __half g_qkh[(size_t)BATCH * SEQ * 2 * DIM];  // Q|K fp16 [8192][2048]
__device__ __half g_vth[RXD];                            // V^T fp16 [B][DV][SEQ]
__device__ __half g_ph[RSS];                             // P = exp(s*scale) fp16
__device__ float  g_rsum[(size_t)BATCH * SEQ];           // row sums of P
__device__ __half g_aoh[RXD];                            // AO fp16 (normalized)
__device__ int    g_cnt[N_CNT];

__device__ __forceinline__ void wait_cnt(int idx, int target) {
    volatile int* p = &g_cnt[idx];
    while (*p < target) __nanosleep(64);
}
__device__ __forceinline__ void publish(int idx) {
    __threadfence();
    atomicAdd(&g_cnt[idx], 1);
}

// ---------------------------------------------------------------------------
// Async tile load: 128 rows x 64 fp16 (K-major) -> padded smem (stride LDT)
// ---------------------------------------------------------------------------
__device__ __forceinline__ void load_tile_async(uint32_t base,
                                                const __half* __restrict__ gp,
                                                int ld, int tid) {
    #pragma unroll
    for (int i = 0; i < 8; i++) {
        int idx = i * GT + tid;           // 0..1023
        int row = idx >> 3;
        int c16 = idx & 7;
        cpa16(base + row * (LDT * 2) + c16 * 16,
              gp + (size_t)row * ld + c16 * 8);
    }
}

// ---------------------------------------------------------------------------
// Persistent megakernel: workers claim items from an ordered atomic queue.
// Items (topological order): prep-x, prep-W, QKV, scores(+exp), PV(/rsum), Wo.
// Deadlock-free: items are claimed in order by RESIDENT workers; the minimal
// unfinished claimed item has all deps (smaller indices) finished, so its
// worker always progresses. No dispatch-order assumption.
// ---------------------------------------------------------------------------
__global__ __launch_bounds__(GT, 2)
void mega(const float* __restrict__ x,
          const float* __restrict__ Wq, const float* __restrict__ Wk,
          const float* __restrict__ Wv, const float* __restrict__ Wo,
          float* __restrict__ out)
{
    const int tid  = threadIdx.x;
    extern __shared__ char smem[];
    __shared__ int s_item;

    const int wid  = tid >> 5;
    const int lane = tid & 31;
    const int warp_m = wid >> 1;          // 0..1
    const int warp_n = wid & 1;           // 0..1
    const int gq = lane >> 2;
    const int tq = lane & 3;

    const int a_r  = lane & 15;
    const int a_kq = (lane >> 4) << 3;
    const int b_r  = (lane & 7) + ((lane >= 16) ? 8 : 0);
    const int b_kq = ((lane >> 3) & 1) << 3;
    const uint32_t sb = smem_u32(smem);
    const uint32_t aoff0 = (warp_m * 64 + a_r) * (LDT * 2) + a_kq * 2;
    const uint32_t boff0 = (warp_n * 64 + b_r) * (LDT * 2) + b_kq * 2;

    for (;;) {
        if (tid == 0) s_item = atomicAdd(&g_cnt[Q_HEAD], 1);
        __syncthreads();
        const int bid = s_item;           // read before next overwrite (end-of-
                                          // item barrier separates iterations)
        if (bid >= N_ALL) return;

        // ================= Prep A: x fp32 -> fp16 =================
        if (bid < N_PX) {
            const int rb = bid >> 2;          // 128-row block 0..63
            const int q  = bid & 3;           // quarter (32 rows)
            const size_t base = ((size_t)rb * 128 + q * 32) * DIM;
            #pragma unroll 8
            for (int i = 0; i < 64; i++) {
                const int idx = i * GT + tid;         // 8192 float4
                float4 v = reinterpret_cast<const float4*>(x + base)[idx];
                uint2 o;
                o.x = pack2h(v.x, v.y);
                o.y = pack2h(v.z, v.w);
                reinterpret_cast<uint2*>(g_xh + base)[idx] = o;
            }
            __syncthreads();
            if (tid == 0) publish(C_X + rb);
            continue;
        }
        // ================= Prep B: weight transpose =================
        if (bid < B_QKV) {
            const int w = bid - N_PX;         // 0..1023
            const int z = w >> 8;             // matrix 0..3
            const int t = w & 255;
            const int tx = t & 15, ty = t >> 4;
            const float* in = (z == 0) ? Wq : (z == 1) ? Wk
                             : (z == 2) ? Wv : Wo;
            __half* dh = (z < 3) ? g_wqkvth + (size_t)z * DIM * DIM : g_woth;
            float* tile = reinterpret_cast<float*>(smem);   // [64][65]
            const int bx = tx * 64, by = ty * 64;
            #pragma unroll
            for (int i = 0; i < 32; i++) {
                const int e = i * GT + tid;
                const int r = e >> 6, c = e & 63;
                tile[r * 65 + c] = in[(size_t)(by + r) * DIM + bx + c];
            }
            __syncthreads();
            #pragma unroll
            for (int i = 0; i < 32; i++) {
                const int e = i * GT + tid;
                const int r = e >> 6, c = e & 63;
                dh[(size_t)(bx + r) * DIM + by + c] =
                    __float2half_rn(tile[c * 65 + r]);
            }
            __syncthreads();
            if (tid == 0) {
                if (z < 3) publish(C_WQ + z * 8 + (tx >> 1));
                else       publish(C_WO + (tx >> 1));
            }
            continue;
        }

        // ================= GEMM items =================
        int mode, row0, col0, zb = 0, nChunks, pubIdx = -1;
        const __half* pA;
        const __half* pB;
        int ldA, ldB;

        if (bid < B_SC) {                                   // ---- QKV ----
            mode = 3;
            const int t = bid - B_QKV;
            const int xb = t % 24, y = t / 24;
            row0 = y * 128; col0 = xb * 128;
            pA = g_xh + (size_t)row0 * DIM;
            pB = g_wqkvth + (size_t)col0 * DIM;
            ldA = DIM; ldB = DIM;
            nChunks = DIM / KC;
            pubIdx = (xb < 16) ? C_QK + y : C_V + y;
            if (tid == 0) {
                wait_cnt(C_X + y, 4);
                wait_cnt(C_WQ + xb, 32);
                __threadfence();
            }
            __syncthreads();
        } else if (bid < B_PV) {                            // ---- scores ----
            mode = 2;
            const int t = bid - B_SC;
            zb = t & 3;
            int tt = t >> 2;                                // r descending
            int r = 15, acc2 = 0;
            while (tt >= acc2 + (r + 1)) { acc2 += r + 1; r--; }
            const int c = tt - acc2;
            row0 = r * 128; col0 = c * 128;
            pA = g_qkh + (size_t)zb * (SEQ * 2 * DIM) + (size_t)row0 * (2 * DIM);
            pB = g_qkh + DIM + (size_t)zb * (SEQ * 2 * DIM) + (size_t)col0 * (2 * DIM);
            ldA = 2 * DIM; ldB = 2 * DIM;
            nChunks = DIM / KC;
            pubIdx = C_SC + zb * 16 + r;
            if (tid == 0) {
                wait_cnt(C_QK + zb * 16 + r, 16);
                wait_cnt(C_QK + zb * 16 + c, 16);
                __threadfence();
            }
            __syncthreads();
        } else if (bid < B_WO) {                            // ---- PV ----
            mode = 1;
            const int t = bid - B_PV;
            zb = t & 3;
            const int u = t >> 2;
            const int r = 15 - (u >> 3);                    // long rows first
            const int xb = u & 7;
            row0 = r * 128; col0 = xb * 128;
            pA = g_ph + (size_t)zb * ((size_t)SEQ * SEQ) + (size_t)row0 * SEQ;
            pB = g_vth + (size_t)zb * ((size_t)DIM * SEQ) + (size_t)col0 * SEQ;
            ldA = SEQ; ldB = SEQ;
            nChunks = ((r + 1) * 128) / KC;
            pubIdx = C_PV + zb * 16 + r;
            if (tid == 0) {
                for (int j = 0; j <= r; j++) wait_cnt(C_V + zb * 16 + j, 8);
                wait_cnt(C_SC + zb * 16 + r, r + 1);
                __threadfence();
            }
            __syncthreads();
        } else {                                            // ---- Wo ----
            mode = 0;
            const int t = bid - B_WO;
            const int q = t >> 3;                           // 0..63
            const int xb = t & 7;
            const int b = q & 3;
            const int r = 15 - (q >> 2);                    // match PV order
            const int m = b * 16 + r;
            row0 = m * 128; col0 = xb * 128;
            pA = g_aoh + (size_t)row0 * DIM;
            pB = g_woth + (size_t)col0 * DIM;
            ldA = DIM; ldB = DIM;
            nChunks = DIM / KC;
            if (tid == 0) {
                wait_cnt(C_PV + m, 8);
                wait_cnt(C_WO + xb, 32);
                __threadfence();
            }
            __syncthreads();
        }

        // ---------------- Shared mainloop ----------------
        float acc[4][8][4];
        #pragma unroll
        for (int i = 0; i < 4; i++)
            #pragma unroll
            for (int j = 0; j < 8; j++)
                #pragma unroll
                for (int q = 0; q < 4; q++) acc[i][j][q] = 0.0f;

        #pragma unroll
        for (int s = 0; s < NS - 1; s++) {
            if (s < nChunks) {
                const uint32_t st = sb + s * STG_B;
                const int k0 = s * KC;
                load_tile_async(st,          pA + k0, ldA, tid);
                load_tile_async(st + TILE_P, pB + k0, ldB, tid);
            }
            cpa_commit();
        }

        uint32_t ah[2][4][4], bh[2][4][4];

        for (int c = 0; c < nChunks; c++) {
            asm volatile("cp.async.wait_group %0;" :: "n"(NS - 2));
            __syncthreads();

            const uint32_t st = sb + (c % NS) * STG_B;

            #pragma unroll
            for (int mb = 0; mb < 4; mb++)
                ldm_x4(ah[0][mb], st + aoff0 + mb * 16 * (LDT * 2));
            #pragma unroll
            for (int nh = 0; nh < 4; nh++)
                ldm_x4(bh[0][nh], st + TILE_P + boff0 + nh * 16 * (LDT * 2));

            #pragma unroll
            for (int ks = 0; ks < 4; ks++) {
                const int cur = ks & 1;
                if (ks < 3) {
                    const uint32_t kb = (ks + 1) * 32;
                    #pragma unroll
                    for (int mb = 0; mb < 4; mb++)
                        ldm_x4(ah[cur ^ 1][mb],
                               st + aoff0 + mb * 16 * (LDT * 2) + kb);
                    #pragma unroll
                    for (int nh = 0; nh < 4; nh++)
                        ldm_x4(bh[cur ^ 1][nh],
                               st + TILE_P + boff0 + nh * 16 * (LDT * 2) + kb);
                }
                #pragma unroll
                for (int mb = 0; mb < 4; mb++) {
                    #pragma unroll
                    for (int nb = 0; nb < 8; nb++) {
                        const int nh = nb >> 1, p = (nb & 1) * 2;
                        mma16816(acc[mb][nb], ah[cur][mb],
                                 bh[cur][nh][p], bh[cur][nh][p + 1]);
                    }
                }
            }

            const int cn = c + NS - 1;
            if (cn < nChunks) {
                const uint32_t stn = sb + (cn % NS) * STG_B;
                const int k0 = cn * KC;
                load_tile_async(stn,          pA + k0, ldA, tid);
                load_tile_async(stn + TILE_P, pB + k0, ldB, tid);
            }
            cpa_commit();
        }
        // drain outstanding (possibly empty) cp.async groups before smem reuse
        asm volatile("cp.async.wait_group 0;");

        // ---------------- Epilogues ----------------
        if (mode == 2) {
            #pragma unroll
            for (int mb = 0; mb < 4; mb++) {
                const int m0 = row0 + warp_m * 64 + mb * 16 + gq;
                const int m1 = m0 + 8;
                float sum0 = 0.0f, sum1 = 0.0f;
                #pragma unroll
                for (int nb = 0; nb < 8; nb++) {
                    const int n = col0 + warp_n * 64 + nb * 8 + tq * 2;
                    const float* cc = acc[mb][nb];
                    float p00 = (n     <= m0) ? __expf(cc[0] * SM_SCALE) : 0.0f;
                    float p01 = (n + 1 <= m0) ? __expf(cc[1] * SM_SCALE) : 0.0f;
                    float p10 = (n     <= m1) ? __expf(cc[2] * SM_SCALE) : 0.0f;
                    float p11 = (n + 1 <= m1) ? __expf(cc[3] * SM_SCALE) : 0.0f;
                    sum0 += p00 + p01;
                    sum1 += p10 + p11;
                    size_t o0 = (size_t)zb * SEQ * SEQ + (size_t)m0 * SEQ + n;
                    size_t o1 = (size_t)zb * SEQ * SEQ + (size_t)m1 * SEQ + n;
                    *reinterpret_cast<uint32_t*>(g_ph + o0) = pack2h(p00, p01);
                    *reinterpret_cast<uint32_t*>(g_ph + o1) = pack2h(p10, p11);
                }
                #pragma unroll
                for (int o = 1; o < 4; o <<= 1) {
                    sum0 += __shfl_xor_sync(0xffffffffu, sum0, o);
                    sum1 += __shfl_xor_sync(0xffffffffu, sum1, o);
                }
                if (tq == 0) {
                    atomicAdd(&g_rsum[(size_t)zb * SEQ + m0], sum0);
                    atomicAdd(&g_rsum[(size_t)zb * SEQ + m1], sum1);
                }
            }
        } else if (mode == 1) {
            #pragma unroll
            for (int mb = 0; mb < 4; mb++) {
                const int m = row0 + warp_m * 64 + mb * 16 + gq;
                const float inv0 = 1.0f / g_rsum[(size_t)zb * SEQ + m];
                const float inv1 = 1.0f / g_rsum[(size_t)zb * SEQ + m + 8];
                #pragma unroll
                for (int nb = 0; nb < 8; nb++) {
                    const int n = col0 + warp_n * 64 + nb * 8 + tq * 2;
                    const float* cc = acc[mb][nb];
                    size_t o0 = (size_t)zb * SEQ * DIM + (size_t)m * DIM + n;
                    size_t o1 = (size_t)zb * SEQ * DIM + (size_t)(m + 8) * DIM + n;
                    *reinterpret_cast<uint32_t*>(g_aoh + o0) =
                        pack2h(cc[0] * inv0, cc[1] * inv0);
                    *reinterpret_cast<uint32_t*>(g_aoh + o1) =
                        pack2h(cc[2] * inv1, cc[3] * inv1);
                }
            }
        } else if (mode == 0) {
            #pragma unroll
            for (int mb = 0; mb < 4; mb++) {
                const int m = row0 + warp_m * 64 + mb * 16 + gq;
                #pragma unroll
                for (int nb = 0; nb < 8; nb++) {
                    const int n = col0 + warp_n * 64 + nb * 8 + tq * 2;
                    const float* cc = acc[mb][nb];
                    float* d0 = out + (size_t)m * DIM + n;
                    float* d1 = out + (size_t)(m + 8) * DIM + n;
                    *reinterpret_cast<float2*>(d0) = make_float2(cc[0], cc[1]);
                    *reinterpret_cast<float2*>(d1) = make_float2(cc[2], cc[3]);
                }
            }
        } else if (col0 < 2048) {
            // QKV, Q|K region -> fp16
            #pragma unroll
            for (int mb = 0; mb < 4; mb++) {
                const int m = row0 + warp_m * 64 + mb * 16 + gq;
                #pragma unroll
                for (int nb = 0; nb < 8; nb++) {
                    const int n = col0 + warp_n * 64 + nb * 8 + tq * 2;
                    const float* cc = acc[mb][nb];
                    size_t o0 = (size_t)m * (2 * DIM) + n;
                    size_t o1 = (size_t)(m + 8) * (2 * DIM) + n;
                    *reinterpret_cast<uint32_t*>(g_qkh + o0) = pack2h(cc[0], cc[1]);
                    *reinterpret_cast<uint32_t*>(g_qkh + o1) = pack2h(cc[2], cc[3]);
                }
            }
        } else {
            // QKV, V^T region: transpose through smem, write fp16
            float* smt = reinterpret_cast<float*>(smem);   // [128][129]
            __syncthreads();
            #pragma unroll
            for (int mb = 0; mb < 4; mb++) {
                const int m = warp_m * 64 + mb * 16 + gq;
                #pragma unroll
                for (int nb = 0; nb < 8; nb++) {
                    const int n = warp_n * 64 + nb * 8 + tq * 2;
                    const float* cc = acc[mb][nb];
                    smt[m * 129 + n]           = cc[0];
                    smt[m * 129 + n + 1]       = cc[1];
                    smt[(m + 8) * 129 + n]     = cc[2];
                    smt[(m + 8) * 129 + n + 1] = cc[3];
                }
            }
            __syncthreads();
            const int b  = row0 >> 11;
            const int s0 = row0 & (SEQ - 1);
            const int nl = tid;
            const size_t base = (size_t)b * DIM * SEQ +
                                (size_t)(col0 - 2048 + nl) * SEQ + s0;
            #pragma unroll
            for (int u = 0; u < 128; u += 2) {
                *reinterpret_cast<uint32_t*>(g_vth + base + u) =
                    pack2h(smt[u * 129 + nl], smt[(u + 1) * 129 + nl]);
            }
        }

        // ---------------- Publish + end-of-item barrier ----------------
        __syncthreads();
        if (tid == 0 && pubIdx >= 0) publish(pubIdx);
    }
}

// ---------------------------------------------------------------------------
// Launch
// ---------------------------------------------------------------------------
extern "C" void kernel_launch(void* const* d_in, const int* in_sizes, int n_in,
                              void* d_out, int out_size)
{
    const float* x  = (const float*)d_in[0];
    const float* Wq = (const float*)d_in[1];
    const float* Wk = (const float*)d_in[2];
    const float* Wv = (const float*)d_in[3];
    const float* Wo = (const float*)d_in[4];
    float* out = (float*)d_out;

    cudaFuncSetAttribute(mega, cudaFuncAttributeMaxDynamicSharedMemorySize, SMEM_B);

    float* rsum;
    int* cnt;
    cudaGetSymbolAddress((void**)&rsum, g_rsum);
    cudaGetSymbolAddress((void**)&cnt, g_cnt);

    // zero counters + queue head + rsum (graph-capturable async memsets)
    cudaMemsetAsync(cnt, 0, N_CNT * sizeof(int));
    cudaMemsetAsync(rsum, 0, (size_t)BATCH * SEQ * sizeof(float));

    // persistent worker pool; provably deadlock-free ordered work queue
    mega<<<NWORKERS, GT, SMEM_B>>>(x, Wq, Wk, Wv, Wo, out);
}

// round 15
// speedup vs baseline: 1.1109x; 1.1109x over previous
#include <cuda_runtime.h>
#include <cuda_fp16.h>
#include <cstdint>
#include <cstddef>

// ---------------------------------------------------------------------------
// Problem constants
// ---------------------------------------------------------------------------
#define BATCH 4
#define SEQ   2048
#define DIM   1024

// GEMM tiling: 128x128 CTA tile, 4 warps of 64x64, K chunks of 64 fp16.
#define KC     64
#define LDT    72                       // padded row stride in fp16 (144 B)
#define TILE_P (128 * LDT * 2)          // 18432 B per tile
#define STG_B  (2 * TILE_P)             // 36864 B (A + B)
#define NS     3                        // pipeline stages
#define SMEM_B (NS * STG_B)             // 110592 B -> 2 CTAs/SM
#define GT     128                      // threads per CTA (4 warps)

#define SM_SCALE 0.03125f               // 1/sqrt(1024)

// Work-queue items (topological order):
//   prep-x | transpose Wq,Wk,Wo | convert Wv | Wvo=Wo^T x Wv | QKV | scores | PV
#define N_PX    256
#define N_PT    768                     // 3 matrices x 256 (64x64 tiles)
#define N_PWV   32                      // Wv fp32->fp16 convert
#define N_WVO   64                      // Wvo^T GEMM tiles (8x8)
#define N_QKV   1536                    // 24 x 64
#define N_SC    544                     // 136 tri-tiles x 4 batches
#define N_PVQ   512                     // 8 x 16 x 4  (writes out directly)
#define B_PT    (N_PX)
#define B_PWV   (B_PT + N_PT)           // 1024
#define B_WVO   (B_PWV + N_PWV)         // 1056
#define B_QKV   (B_WVO + N_WVO)         // 1120
#define B_SC    (B_QKV + N_QKV)         // 2656
#define B_PV    (B_SC + N_SC)           // 3200
#define N_ALL   (B_PV + N_PVQ)          // 3712

#define NWORKERS 304

// Counter layout
#define C_QK   0                        // [0:64)   qk row-blocks, target 16
#define C_V    64                       // [64:128) v' row-blocks, target 8
#define C_SC   128                      // [128:192) scores rows, target r+1
#define C_X    192                      // [192:256) x row-blocks, target 4
#define C_WQ   256                      // [256:272) Wq|Wk^T col-blocks, 32
#define C_WO   272                      // [272:280) Wo^T row-blocks, 32
#define C_WV   280                      // [280:288) Wv fp16 row-blocks, 4
#define C_WVO  288                      // [288:296) Wvo^T row-blocks, 8
#define Q_HEAD 320
#define N_CNT  512

// ---------------------------------------------------------------------------
// PTX helpers (base sm_103 ISA: cp.async, ldmatrix, mma.sync)
// ---------------------------------------------------------------------------
__device__ __forceinline__ uint32_t smem_u32(const void* p) {
    uint32_t a;
    asm("{ .reg .u64 t; cvta.to.shared.u64 t, %1; cvt.u32.u64 %0, t; }"
        : "=r"(a) : "l"(p));
    return a;
}
__device__ __forceinline__ void cpa16(uint32_t dst, const void* src) {
    asm volatile("cp.async.cg.shared.global [%0], [%1], 16;"
                 :: "r"(dst), "l"(src));
}
__device__ __forceinline__ void cpa_commit() {
    asm volatile("cp.async.commit_group;");
}
__device__ __forceinline__ void ldm_x4(uint32_t* r, uint32_t addr) {
    asm volatile("ldmatrix.sync.aligned.m8n8.x4.shared.b16 {%0,%1,%2,%3}, [%4];"
                 : "=r"(r[0]), "=r"(r[1]), "=r"(r[2]), "=r"(r[3]) : "r"(addr));
}
__device__ __forceinline__ void mma16816(float* d, const uint32_t* a,
                                         uint32_t b0, uint32_t b1) {
    asm volatile(
        "mma.sync.aligned.m16n8k16.row.col.f32.f16.f16.f32 "
        "{%0,%1,%2,%3}, {%4,%5,%6,%7}, {%8,%9}, {%0,%1,%2,%3};"
        : "+f"(d[0]), "+f"(d[1]), "+f"(d[2]), "+f"(d[3])
        : "r"(a[0]), "r"(a[1]), "r"(a[2]), "r"(a[3]), "r"(b0), "r"(b1));
}
__device__ __forceinline__ uint32_t pack2h(float a, float b) {
    __half ha = __float2half_rn(a), hb = __float2half_rn(b);
    return (uint32_t)__half_as_ushort(ha) | ((uint32_t)__half_as_ushort(hb) << 16);
}

// ---------------------------------------------------------------------------
// Device scratch + dependency counters
// ---------------------------------------------------------------------------
#define RXD ((size_t)BATCH * SEQ * DIM)
#define RSS ((size_t)BATCH * SEQ * SEQ)
__device__ __half g_xh[RXD];                             // x fp16
__device__ __half g_qkvth[2 * DIM * DIM];                // Wq^T|Wk^T fp16
__device__ __half g_woth[DIM * DIM];                     // Wo^T fp16
__device__ __half g_wvh[DIM * DIM];                      // Wv fp16 (natural)
__device__ __half g_wvoth[DIM * DIM];                    // (Wv@Wo)^T fp16
__device__ __half g_qkh[(size_t)BATCH * SEQ * 2 * DIM];  // Q|K fp16 [8192][2048]
__device__ __half g_vth[RXD];                            // V'^T fp16 [B][DV][SEQ]
__device__ __half g_ph[RSS];                             // P = exp(s*scale) fp16
__device__ float  g_rsum[(size_t)BATCH * SEQ];           // row sums of P
__device__ int    g_cnt[N_CNT];

__device__ __forceinline__ void wait_cnt(int idx, int target) {
    volatile int* p = &g_cnt[idx];
    while (*p < target) __nanosleep(64);
}
__device__ __forceinline__ void publish(int idx) {
    __threadfence();
    atomicAdd(&g_cnt[idx], 1);
}

// ---------------------------------------------------------------------------
// Async tile load: 128 rows x 64 fp16 (K-major) -> padded smem (stride LDT)
// ---------------------------------------------------------------------------
__device__ __forceinline__ void load_tile_async(uint32_t base,
                                                const __half* __restrict__ gp,
                                                int ld, int tid) {
    #pragma unroll
    for (int i = 0; i < 8; i++) {
        int idx = i * GT + tid;           // 0..1023
        int row = idx >> 3;
        int c16 = idx & 7;
        cpa16(base + row * (LDT * 2) + c16 * 16,
              gp + (size_t)row * ld + c16 * 8);
    }
}

// fp32 -> fp16 block convert: 32 rows of DIM floats
__device__ __forceinline__ void conv_rows(const float* __restrict__ src,
                                          __half* __restrict__ dst, int tid) {
    #pragma unroll 8
    for (int i = 0; i < 64; i++) {
        const int idx = i * GT + tid;     // 8192 float4
        float4 v = reinterpret_cast<const float4*>(src)[idx];
        uint2 o;
        o.x = pack2h(v.x, v.y);
        o.y = pack2h(v.z, v.w);
        reinterpret_cast<uint2*>(dst)[idx] = o;
    }
}

// ---------------------------------------------------------------------------
// Persistent megakernel, ordered atomic work queue (deadlock-free: items are
// claimed in topological order by resident workers).
// ---------------------------------------------------------------------------
__global__ __launch_bounds__(GT, 2)
void mega(const float* __restrict__ x,
          const float* __restrict__ Wq, const float* __restrict__ Wk,
          const float* __restrict__ Wv, const float* __restrict__ Wo,
          float* __restrict__ out)
{
    const int tid  = threadIdx.x;
    extern __shared__ char smem[];
    __shared__ int s_item;

    const int wid  = tid >> 5;
    const int lane = tid & 31;
    const int warp_m = wid >> 1;
    const int warp_n = wid & 1;
    const int gq = lane >> 2;
    const int tq = lane & 3;

    const int a_r  = lane & 15;
    const int a_kq = (lane >> 4) << 3;
    const int b_r  = (lane & 7) + ((lane >= 16) ? 8 : 0);
    const int b_kq = ((lane >> 3) & 1) << 3;
    const uint32_t sb = smem_u32(smem);
    const uint32_t aoff0 = (warp_m * 64 + a_r) * (LDT * 2) + a_kq * 2;
    const uint32_t boff0 = (warp_n * 64 + b_r) * (LDT * 2) + b_kq * 2;

    for (;;) {
        if (tid == 0) s_item = atomicAdd(&g_cnt[Q_HEAD], 1);
        __syncthreads();
        const int bid = s_item;
        if (bid >= N_ALL) return;

        // ============ Prep A: x fp32 -> fp16 ============
        if (bid < B_PT) {
            const int rb = bid >> 2;          // 128-row block 0..63
            const int q  = bid & 3;
            const size_t base = ((size_t)rb * 128 + q * 32) * DIM;
            conv_rows(x + base, g_xh + base, tid);
            __syncthreads();
            if (tid == 0) publish(C_X + rb);
            continue;
        }
        // ============ Prep B: transpose Wq, Wk, Wo ============
        if (bid < B_PWV) {
            const int w = bid - B_PT;         // 0..767
            const int z = w >> 8;             // 0=Wq 1=Wk 2=Wo
            const int t = w & 255;
            const int tx = t & 15, ty = t >> 4;
            const float* in = (z == 0) ? Wq : (z == 1) ? Wk : Wo;
            __half* dh = (z < 2) ? g_qkvth + (size_t)z * DIM * DIM : g_woth;
            float* tile = reinterpret_cast<float*>(smem);   // [64][65]
            const int bx = tx * 64, by = ty * 64;
            #pragma unroll
            for (int i = 0; i < 32; i++) {
                const int e = i * GT + tid;
                const int r = e >> 6, c = e & 63;
                tile[r * 65 + c] = in[(size_t)(by + r) * DIM + bx + c];
            }
            __syncthreads();
            #pragma unroll
            for (int i = 0; i < 32; i++) {
                const int e = i * GT + tid;
                const int r = e >> 6, c = e & 63;
                dh[(size_t)(bx + r) * DIM + by + c] =
                    __float2half_rn(tile[c * 65 + r]);
            }
            __syncthreads();
            if (tid == 0) {
                if (z < 2) publish(C_WQ + z * 8 + (tx >> 1));
                else       publish(C_WO + (tx >> 1));
            }
            continue;
        }
        // ============ Prep C: Wv fp32 -> fp16 (no transpose) ============
        if (bid < B_WVO) {
            const int w = bid - B_PWV;        // 0..31, 32 rows each
            const size_t base = (size_t)w * 32 * DIM;
            conv_rows(Wv + base, g_wvh + base, tid);
            __syncthreads();
            if (tid == 0) publish(C_WV + (w >> 2));
            continue;
        }

        // ============ GEMM items ============
        // mode: 4 = Wvo^T fp16 out, 3 = fused QKV, 2 = scores+exp, 1 = PV->out
        int mode, row0, col0, zb = 0, nChunks, pubIdx = -1;
        const __half* pA;
        const __half* pB;
        int ldA, ldB;

        if (bid < B_QKV) {                                  // ---- Wvo ----
            // Wvo^T[n][k] = sum_j Wo[j][n] * Wv[k][j]; A=Wo^T, B=Wv
            mode = 4;
            const int t = bid - B_WVO;
            const int rw = t >> 3, cb = t & 7;
            row0 = rw * 128; col0 = cb * 128;
            pA = g_woth + (size_t)row0 * DIM;
            pB = g_wvh + (size_t)col0 * DIM;
            ldA = DIM; ldB = DIM;
            nChunks = DIM / KC;
            pubIdx = C_WVO + rw;
            if (tid == 0) {
                wait_cnt(C_WO + rw, 32);
                wait_cnt(C_WV + cb, 4);
                __threadfence();
            }
            __syncthreads();
        } else if (bid < B_SC) {                            // ---- QKV ----
            mode = 3;
            const int t = bid - B_QKV;
            const int xb = t % 24, y = t / 24;
            row0 = y * 128; col0 = xb * 128;
            pA = g_xh + (size_t)row0 * DIM;
            ldA = DIM; ldB = DIM;
            nChunks = DIM / KC;
            if (xb < 16) {
                pB = g_qkvth + (size_t)col0 * DIM;
                pubIdx = C_QK + y;
            } else {
                pB = g_wvoth + (size_t)(xb - 16) * 128 * DIM;
                pubIdx = C_V + y;
            }
            if (tid == 0) {
                wait_cnt(C_X + y, 4);
                if (xb < 16) wait_cnt(C_WQ + xb, 32);
                else         wait_cnt(C_WVO + (xb - 16), 8);
                __threadfence();
            }
            __syncthreads();
        } else if (bid < B_PV) {                            // ---- scores ----
            mode = 2;
            const int t = bid - B_SC;
            zb = t & 3;
            int tt = t >> 2;                                // r descending
            int r = 15, acc2 = 0;
            while (tt >= acc2 + (r + 1)) { acc2 += r + 1; r--; }
            const int c = tt - acc2;
            row0 = r * 128; col0 = c * 128;
            pA = g_qkh + (size_t)zb * (SEQ * 2 * DIM) + (size_t)row0 * (2 * DIM);
            pB = g_qkh + DIM + (size_t)zb * (SEQ * 2 * DIM) + (size_t)col0 * (2 * DIM);
            ldA = 2 * DIM; ldB = 2 * DIM;
            nChunks = DIM / KC;
            pubIdx = C_SC + zb * 16 + r;
            if (tid == 0) {
                wait_cnt(C_QK + zb * 16 + r, 16);
                wait_cnt(C_QK + zb * 16 + c, 16);
                __threadfence();
            }
            __syncthreads();
        } else {                                            // ---- PV -> out --
            mode = 1;
            const int t = bid - B_PV;
            zb = t & 3;
            const int u = t >> 2;
            const int r = 15 - (u >> 3);                    // long rows first
            const int xb = u & 7;
            row0 = r * 128; col0 = xb * 128;
            pA = g_ph + (size_t)zb * ((size_t)SEQ * SEQ) + (size_t)row0 * SEQ;
            pB = g_vth + (size_t)zb * ((size_t)DIM * SEQ) + (size_t)col0 * SEQ;
            ldA = SEQ; ldB = SEQ;
            nChunks = ((r + 1) * 128) / KC;
            if (tid == 0) {
                for (int j = 0; j <= r; j++) wait_cnt(C_V + zb * 16 + j, 8);
                wait_cnt(C_SC + zb * 16 + r, r + 1);
                __threadfence();
            }
            __syncthreads();
        }

        // ---------------- Shared mainloop ----------------
        float acc[4][8][4];
        #pragma unroll
        for (int i = 0; i < 4; i++)
            #pragma unroll
            for (int j = 0; j < 8; j++)
                #pragma unroll
                for (int q = 0; q < 4; q++) acc[i][j][q] = 0.0f;

        #pragma unroll
        for (int s = 0; s < NS - 1; s++) {
            if (s < nChunks) {
                const uint32_t st = sb + s * STG_B;
                const int k0 = s * KC;
                load_tile_async(st,          pA + k0, ldA, tid);
                load_tile_async(st + TILE_P, pB + k0, ldB, tid);
            }
            cpa_commit();
        }

        uint32_t ah[2][4][4], bh[2][4][4];

        for (int c = 0; c < nChunks; c++) {
            asm volatile("cp.async.wait_group %0;" :: "n"(NS - 2));
            __syncthreads();

            const uint32_t st = sb + (c % NS) * STG_B;

            #pragma unroll
            for (int mb = 0; mb < 4; mb++)
                ldm_x4(ah[0][mb], st + aoff0 + mb * 16 * (LDT * 2));
            #pragma unroll
            for (int nh = 0; nh < 4; nh++)
                ldm_x4(bh[0][nh], st + TILE_P + boff0 + nh * 16 * (LDT * 2));

            #pragma unroll
            for (int ks = 0; ks < 4; ks++) {
                const int cur = ks & 1;
                if (ks < 3) {
                    const uint32_t kb = (ks + 1) * 32;
                    #pragma unroll
                    for (int mb = 0; mb < 4; mb++)
                        ldm_x4(ah[cur ^ 1][mb],
                               st + aoff0 + mb * 16 * (LDT * 2) + kb);
                    #pragma unroll
                    for (int nh = 0; nh < 4; nh++)
                        ldm_x4(bh[cur ^ 1][nh],
                               st + TILE_P + boff0 + nh * 16 * (LDT * 2) + kb);
                }
                #pragma unroll
                for (int mb = 0; mb < 4; mb++) {
                    #pragma unroll
                    for (int nb = 0; nb < 8; nb++) {
                        const int nh = nb >> 1, p = (nb & 1) * 2;
                        mma16816(acc[mb][nb], ah[cur][mb],
                                 bh[cur][nh][p], bh[cur][nh][p + 1]);
                    }
                }
            }

            const int cn = c + NS - 1;
            if (cn < nChunks) {
                const uint32_t stn = sb + (cn % NS) * STG_B;
                const int k0 = cn * KC;
                load_tile_async(stn,          pA + k0, ldA, tid);
                load_tile_async(stn + TILE_P, pB + k0, ldB, tid);
            }
            cpa_commit();
        }
        asm volatile("cp.async.wait_group 0;");   // drain before smem reuse

        // ---------------- Epilogues ----------------
        if (mode == 2) {
            // scores -> P = exp(scale*s) masked, fp16 + row-sum atomics
            #pragma unroll
            for (int mb = 0; mb < 4; mb++) {
                const int m0 = row0 + warp_m * 64 + mb * 16 + gq;
                const int m1 = m0 + 8;
                float sum0 = 0.0f, sum1 = 0.0f;
                #pragma unroll
                for (int nb = 0; nb < 8; nb++) {
                    const int n = col0 + warp_n * 64 + nb * 8 + tq * 2;
                    const float* cc = acc[mb][nb];
                    float p00 = (n     <= m0) ? __expf(cc[0] * SM_SCALE) : 0.0f;
                    float p01 = (n + 1 <= m0) ? __expf(cc[1] * SM_SCALE) : 0.0f;
                    float p10 = (n     <= m1) ? __expf(cc[2] * SM_SCALE) : 0.0f;
                    float p11 = (n + 1 <= m1) ? __expf(cc[3] * SM_SCALE) : 0.0f;
                    sum0 += p00 + p01;
                    sum1 += p10 + p11;
                    size_t o0 = (size_t)zb * SEQ * SEQ + (size_t)m0 * SEQ + n;
                    size_t o1 = (size_t)zb * SEQ * SEQ + (size_t)m1 * SEQ + n;
                    *reinterpret_cast<uint32_t*>(g_ph + o0) = pack2h(p00, p01);
                    *reinterpret_cast<uint32_t*>(g_ph + o1) = pack2h(p10, p11);
                }
                #pragma unroll
                for (int o = 1; o < 4; o <<= 1) {
                    sum0 += __shfl_xor_sync(0xffffffffu, sum0, o);
                    sum1 += __shfl_xor_sync(0xffffffffu, sum1, o);
                }
                if (tq == 0) {
                    atomicAdd(&g_rsum[(size_t)zb * SEQ + m0], sum0);
                    atomicAdd(&g_rsum[(size_t)zb * SEQ + m1], sum1);
                }
            }
        } else if (mode == 1) {
            // PV -> out = acc / rsum, fp32 (FINAL)
            #pragma unroll
            for (int mb = 0; mb < 4; mb++) {
                const int m = row0 + warp_m * 64 + mb * 16 + gq;
                const float inv0 = 1.0f / g_rsum[(size_t)zb * SEQ + m];
                const float inv1 = 1.0f / g_rsum[(size_t)zb * SEQ + m + 8];
                #pragma unroll
                for (int nb = 0; nb < 8; nb++) {
                    const int n = col0 + warp_n * 64 + nb * 8 + tq * 2;
                    const float* cc = acc[mb][nb];
                    float* d0 = out + ((size_t)zb * SEQ + m) * DIM + n;
                    float* d1 = out + ((size_t)zb * SEQ + m + 8) * DIM + n;
                    *reinterpret_cast<float2*>(d0) =
                        make_float2(cc[0] * inv0, cc[1] * inv0);
                    *reinterpret_cast<float2*>(d1) =
                        make_float2(cc[2] * inv1, cc[3] * inv1);
                }
            }
        } else if (mode == 4) {
            // Wvo^T fp16 out
            #pragma unroll
            for (int mb = 0; mb < 4; mb++) {
                const int m = row0 + warp_m * 64 + mb * 16 + gq;
                #pragma unroll
                for (int nb = 0; nb < 8; nb++) {
                    const int n = col0 + warp_n * 64 + nb * 8 + tq * 2;
                    const float* cc = acc[mb][nb];
                    size_t o0 = (size_t)m * DIM + n;
                    size_t o1 = (size_t)(m + 8) * DIM + n;
                    *reinterpret_cast<uint32_t*>(g_wvoth + o0) = pack2h(cc[0], cc[1]);
                    *reinterpret_cast<uint32_t*>(g_wvoth + o1) = pack2h(cc[2], cc[3]);
                }
            }
        } else if (col0 < 2048) {
            // QKV, Q|K region -> fp16
            #pragma unroll
            for (int mb = 0; mb < 4; mb++) {
                const int m = row0 + warp_m * 64 + mb * 16 + gq;
                #pragma unroll
                for (int nb = 0; nb < 8; nb++) {
                    const int n = col0 + warp_n * 64 + nb * 8 + tq * 2;
                    const float* cc = acc[mb][nb];
                    size_t o0 = (size_t)m * (2 * DIM) + n;
                    size_t o1 = (size_t)(m + 8) * (2 * DIM) + n;
                    *reinterpret_cast<uint32_t*>(g_qkh + o0) = pack2h(cc[0], cc[1]);
                    *reinterpret_cast<uint32_t*>(g_qkh + o1) = pack2h(cc[2], cc[3]);
                }
            }
        } else {
            // QKV, V' region: transpose through smem, write fp16 V'^T
            float* smt = reinterpret_cast<float*>(smem);   // [128][129]
            __syncthreads();
            #pragma unroll
            for (int mb = 0; mb < 4; mb++) {
                const int m = warp_m * 64 + mb * 16 + gq;
                #pragma unroll
                for (int nb = 0; nb < 8; nb++) {
                    const int n = warp_n * 64 + nb * 8 + tq * 2;
                    const float* cc = acc[mb][nb];
                    smt[m * 129 + n]           = cc[0];
                    smt[m * 129 + n + 1]       = cc[1];
                    smt[(m + 8) * 129 + n]     = cc[2];
                    smt[(m + 8) * 129 + n + 1] = cc[3];
                }
            }
            __syncthreads();
            const int b  = row0 >> 11;
            const int s0 = row0 & (SEQ - 1);
            const int nl = tid;
            const size_t base = (size_t)b * DIM * SEQ +
                                (size_t)(col0 - 2048 + nl) * SEQ + s0;
            #pragma unroll
            for (int u = 0; u < 128; u += 2) {
                *reinterpret_cast<uint32_t*>(g_vth + base + u) =
                    pack2h(smt[u * 129 + nl], smt[(u + 1) * 129 + nl]);
            }
        }

        // ---------------- Publish + end-of-item barrier ----------------
        __syncthreads();
        if (tid == 0 && pubIdx >= 0) publish(pubIdx);
    }
}

// ---------------------------------------------------------------------------
// Launch
// ---------------------------------------------------------------------------
extern "C" void kernel_launch(void* const* d_in, const int* in_sizes, int n_in,
                              void* d_out, int out_size)
{
    const float* x  = (const float*)d_in[0];
    const float* Wq = (const float*)d_in[1];
    const float* Wk = (const float*)d_in[2];
    const float* Wv = (const float*)d_in[3];
    const float* Wo = (const float*)d_in[4];
    float* out = (float*)d_out;

    cudaFuncSetAttribute(mega, cudaFuncAttributeMaxDynamicSharedMemorySize, SMEM_B);

    float* rsum;
    int* cnt;
    cudaGetSymbolAddress((void**)&rsum, g_rsum);
    cudaGetSymbolAddress((void**)&cnt, g_cnt);

    cudaMemsetAsync(cnt, 0, N_CNT * sizeof(int));
    cudaMemsetAsync(rsum, 0, (size_t)BATCH * SEQ * sizeof(float));

    mega<<<NWORKERS, GT, SMEM_B>>>(x, Wq, Wk, Wv, Wo, out);
}

// round 16
// speedup vs baseline: 1.2391x; 1.1154x over previous
#include <cuda_runtime.h>
#include <cuda_fp16.h>
#include <cstdint>
#include <cstddef>

// ---------------------------------------------------------------------------
// Problem constants
// ---------------------------------------------------------------------------
#define BATCH 4
#define SEQ   2048
#define DIM   1024

// GEMM tiling: 128x128 CTA tile, 4 warps of 64x64, K chunks of 64 fp16.
#define KC     64
#define LDT    72                       // padded row stride in fp16 (144 B)
#define TILE_P (128 * LDT * 2)          // 18432 B per tile
#define STG_B  (2 * TILE_P)             // 36864 B (A + B)
#define NS     3                        // pipeline stages
#define SMEM_B (NS * STG_B)             // 110592 B -> 2 CTAs/SM
#define GT     128                      // threads per CTA (4 warps)

#define SM_SCALE 0.03125f               // 1/sqrt(1024)

// Work-queue items (topological order):
//   x conv | Wq,Wk,Wv natural conv | Wo transpose | Wqk^T | Wvo^T |
//   proj (Q'|V') | scores(+exp) | PV -> out
#define N_PX    256
#define B_WN    256                     // natural converts (3 x 32 items)
#define N_WN    96
#define B_WOT   352                     // Wo transpose tiles
#define N_WOT   256
#define B_WQK   608                     // Wqk^T = Wk x Wq^T, 8x8 tiles
#define B_WVO   672                     // Wvo^T = Wo^T x Wv, 8x8 tiles
#define B_PROJ  736                     // Q'|V' = x @ [Wqk|Wvo], 16 x 64
#define N_PROJ  1024
#define B_SC2   1760                    // scores, 136 x 4
#define N_SC    544
#define B_PV2   2304                    // PV, 512
#define N_PVQ   512
#define N_ALL   2816

#define NWORKERS 304

// Counter layout
#define C_X    0                        // [0:64)    x blocks, target 4
#define C_WQN  64                       // [64:72)   Wq fp16 blocks, target 4
#define C_WKN  72                       // [72:80)   Wk fp16 blocks, target 4
#define C_WVN  80                       // [80:88)   Wv fp16 blocks, target 4
#define C_WOT  88                       // [88:96)   Wo^T row-blocks, target 32
#define C_WQK  96                       // [96:104)  Wqk^T row-blocks, target 8
#define C_WVO  104                      // [104:112) Wvo^T row-blocks, target 8
#define C_Q    112                      // [112:176) Q' row-blocks, target 8
#define C_V    176                      // [176:240) V' row-blocks, target 8
#define C_SC   240                      // [240:304) scores rows, target r+1
#define Q_HEAD 320
#define N_CNT  512

// ---------------------------------------------------------------------------
// PTX helpers (base sm_103 ISA: cp.async, ldmatrix, mma.sync)
// ---------------------------------------------------------------------------
__device__ __forceinline__ uint32_t smem_u32(const void* p) {
    uint32_t a;
    asm("{ .reg .u64 t; cvta.to.shared.u64 t, %1; cvt.u32.u64 %0, t; }"
        : "=r"(a) : "l"(p));
    return a;
}
__device__ __forceinline__ void cpa16(uint32_t dst, const void* src) {
    asm volatile("cp.async.cg.shared.global [%0], [%1], 16;"
                 :: "r"(dst), "l"(src));
}
__device__ __forceinline__ void cpa_commit() {
    asm volatile("cp.async.commit_group;");
}
__device__ __forceinline__ void ldm_x4(uint32_t* r, uint32_t addr) {
    asm volatile("ldmatrix.sync.aligned.m8n8.x4.shared.b16 {%0,%1,%2,%3}, [%4];"
                 : "=r"(r[0]), "=r"(r[1]), "=r"(r[2]), "=r"(r[3]) : "r"(addr));
}
__device__ __forceinline__ void mma16816(float* d, const uint32_t* a,
                                         uint32_t b0, uint32_t b1) {
    asm volatile(
        "mma.sync.aligned.m16n8k16.row.col.f32.f16.f16.f32 "
        "{%0,%1,%2,%3}, {%4,%5,%6,%7}, {%8,%9}, {%0,%1,%2,%3};"
        : "+f"(d[0]), "+f"(d[1]), "+f"(d[2]), "+f"(d[3])
        : "r"(a[0]), "r"(a[1]), "r"(a[2]), "r"(a[3]), "r"(b0), "r"(b1));
}
__device__ __forceinline__ uint32_t pack2h(float a, float b) {
    __half ha = __float2half_rn(a), hb = __float2half_rn(b);
    return (uint32_t)__half_as_ushort(ha) | ((uint32_t)__half_as_ushort(hb) << 16);
}

// ---------------------------------------------------------------------------
// Device scratch + dependency counters
// ---------------------------------------------------------------------------
#define RXD ((size_t)BATCH * SEQ * DIM)
#define RSS ((size_t)BATCH * SEQ * SEQ)
__device__ __half g_xh[RXD];                 // x fp16 (A of proj, B of scores)
__device__ __half g_wqh[DIM * DIM];          // Wq fp16 natural
__device__ __half g_wkh[DIM * DIM];          // Wk fp16 natural
__device__ __half g_wvh[DIM * DIM];          // Wv fp16 natural
__device__ __half g_woth[DIM * DIM];         // Wo^T fp16
__device__ __half g_wqkth[DIM * DIM];        // (Wq@Wk^T)^T fp16
__device__ __half g_wvoth[DIM * DIM];        // (Wv@Wo)^T fp16
__device__ __half g_qh[RXD];                 // Q' fp16 [8192][1024]
__device__ __half g_vth[RXD];                // V'^T fp16 [B][DV][SEQ]
__device__ __half g_ph[RSS];                 // P = exp(s*scale) fp16
__device__ float  g_rsum[(size_t)BATCH * SEQ];
__device__ int    g_cnt[N_CNT];

__device__ __forceinline__ void wait_cnt(int idx, int target) {
    volatile int* p = &g_cnt[idx];
    while (*p < target) __nanosleep(64);
}
__device__ __forceinline__ void publish(int idx) {
    __threadfence();
    atomicAdd(&g_cnt[idx], 1);
}

// ---------------------------------------------------------------------------
// Async tile load: 128 rows x 64 fp16 (K-major) -> padded smem (stride LDT)
// ---------------------------------------------------------------------------
__device__ __forceinline__ void load_tile_async(uint32_t base,
                                                const __half* __restrict__ gp,
                                                int ld, int tid) {
    #pragma unroll
    for (int i = 0; i < 8; i++) {
        int idx = i * GT + tid;           // 0..1023
        int row = idx >> 3;
        int c16 = idx & 7;
        cpa16(base + row * (LDT * 2) + c16 * 16,
              gp + (size_t)row * ld + c16 * 8);
    }
}

// fp32 -> fp16 block convert: 32 rows of DIM floats
__device__ __forceinline__ void conv_rows(const float* __restrict__ src,
                                          __half* __restrict__ dst, int tid) {
    #pragma unroll 8
    for (int i = 0; i < 64; i++) {
        const int idx = i * GT + tid;     // 8192 float4
        float4 v = reinterpret_cast<const float4*>(src)[idx];
        uint2 o;
        o.x = pack2h(v.x, v.y);
        o.y = pack2h(v.z, v.w);
        reinterpret_cast<uint2*>(dst)[idx] = o;
    }
}

// ---------------------------------------------------------------------------
// Persistent megakernel, ordered atomic work queue (deadlock-free).
// ---------------------------------------------------------------------------
__global__ __launch_bounds__(GT, 2)
void mega(const float* __restrict__ x,
          const float* __restrict__ Wq, const float* __restrict__ Wk,
          const float* __restrict__ Wv, const float* __restrict__ Wo,
          float* __restrict__ out)
{
    const int tid  = threadIdx.x;
    extern __shared__ char smem[];
    __shared__ int s_item;

    const int wid  = tid >> 5;
    const int lane = tid & 31;
    const int warp_m = wid >> 1;
    const int warp_n = wid & 1;
    const int gq = lane >> 2;
    const int tq = lane & 3;

    const int a_r  = lane & 15;
    const int a_kq = (lane >> 4) << 3;
    const int b_r  = (lane & 7) + ((lane >= 16) ? 8 : 0);
    const int b_kq = ((lane >> 3) & 1) << 3;
    const uint32_t sb = smem_u32(smem);
    const uint32_t aoff0 = (warp_m * 64 + a_r) * (LDT * 2) + a_kq * 2;
    const uint32_t boff0 = (warp_n * 64 + b_r) * (LDT * 2) + b_kq * 2;

    for (;;) {
        if (tid == 0) s_item = atomicAdd(&g_cnt[Q_HEAD], 1);
        __syncthreads();
        const int bid = s_item;
        if (bid >= N_ALL) return;

        // ============ Prep A: x fp32 -> fp16 ============
        if (bid < B_WN) {
            const int rb = bid >> 2;
            const int q  = bid & 3;
            const size_t base = ((size_t)rb * 128 + q * 32) * DIM;
            conv_rows(x + base, g_xh + base, tid);
            __syncthreads();
            if (tid == 0) publish(C_X + rb);
            continue;
        }
        // ============ Prep B: Wq, Wk, Wv natural converts ============
        if (bid < B_WOT) {
            const int w = bid - B_WN;         // 0..95
            const int z = w >> 5;             // 0=Wq 1=Wk 2=Wv
            const int r32 = w & 31;
            const float* in = (z == 0) ? Wq : (z == 1) ? Wk : Wv;
            __half* dh = (z == 0) ? g_wqh : (z == 1) ? g_wkh : g_wvh;
            const size_t base = (size_t)r32 * 32 * DIM;
            conv_rows(in + base, dh + base, tid);
            __syncthreads();
            if (tid == 0) publish(((z == 0) ? C_WQN : (z == 1) ? C_WKN : C_WVN)
                                  + (r32 >> 2));
            continue;
        }
        // ============ Prep C: Wo transpose ============
        if (bid < B_WQK) {
            const int t = bid - B_WOT;        // 0..255
            const int tx = t & 15, ty = t >> 4;
            float* tile = reinterpret_cast<float*>(smem);   // [64][65]
            const int bx = tx * 64, by = ty * 64;
            #pragma unroll
            for (int i = 0; i < 32; i++) {
                const int e = i * GT + tid;
                const int r = e >> 6, c = e & 63;
                tile[r * 65 + c] = Wo[(size_t)(by + r) * DIM + bx + c];
            }
            __syncthreads();
            #pragma unroll
            for (int i = 0; i < 32; i++) {
                const int e = i * GT + tid;
                const int r = e >> 6, c = e & 63;
                g_woth[(size_t)(bx + r) * DIM + by + c] =
                    __float2half_rn(tile[c * 65 + r]);
            }
            __syncthreads();
            if (tid == 0) publish(C_WOT + (tx >> 1));
            continue;
        }

        // ============ GEMM items ============
        // mode: 5 = Wqk^T out, 4 = Wvo^T out, 3 = proj (Q'|V'), 2 = scores,
        //       1 = PV -> out
        int mode, row0, col0, zb = 0, nChunks, pubIdx = -1;
        const __half* pA;
        const __half* pB;
        int ldA, ldB;

        if (bid < B_WVO) {                                  // ---- Wqk^T ----
            // Wqk^T[n][k] = sum_j Wk[n][j]*Wq[k][j]; A=Wk, B=Wq (natural)
            mode = 5;
            const int t = bid - B_WQK;
            const int rw = t >> 3, cb = t & 7;
            row0 = rw * 128; col0 = cb * 128;
            pA = g_wkh + (size_t)row0 * DIM;
            pB = g_wqh + (size_t)col0 * DIM;
            ldA = DIM; ldB = DIM;
            nChunks = DIM / KC;
            pubIdx = C_WQK + rw;
            if (tid == 0) {
                wait_cnt(C_WKN + rw, 4);
                wait_cnt(C_WQN + cb, 4);
                __threadfence();
            }
            __syncthreads();
        } else if (bid < B_PROJ) {                          // ---- Wvo^T ----
            mode = 4;
            const int t = bid - B_WVO;
            const int rw = t >> 3, cb = t & 7;
            row0 = rw * 128; col0 = cb * 128;
            pA = g_woth + (size_t)row0 * DIM;
            pB = g_wvh + (size_t)col0 * DIM;
            ldA = DIM; ldB = DIM;
            nChunks = DIM / KC;
            pubIdx = C_WVO + rw;
            if (tid == 0) {
                wait_cnt(C_WOT + rw, 32);
                wait_cnt(C_WVN + cb, 4);
                __threadfence();
            }
            __syncthreads();
        } else if (bid < B_SC2) {                           // ---- proj ----
            mode = 3;
            const int t = bid - B_PROJ;
            const int xb = t & 15, y = t >> 4;
            row0 = y * 128; col0 = xb * 128;
            pA = g_xh + (size_t)row0 * DIM;
            ldA = DIM; ldB = DIM;
            nChunks = DIM / KC;
            if (xb < 8) {
                pB = g_wqkth + (size_t)col0 * DIM;
                pubIdx = C_Q + y;
            } else {
                pB = g_wvoth + (size_t)(xb - 8) * 128 * DIM;
                pubIdx = C_V + y;
            }
            if (tid == 0) {
                wait_cnt(C_X + y, 4);
                if (xb < 8) wait_cnt(C_WQK + xb, 8);
                else        wait_cnt(C_WVO + (xb - 8), 8);
                __threadfence();
            }
            __syncthreads();
        } else if (bid < B_PV2) {                           // ---- scores ----
            mode = 2;
            const int t = bid - B_SC2;
            zb = t & 3;
            int tt = t >> 2;                                // r descending
            int r = 15, acc2 = 0;
            while (tt >= acc2 + (r + 1)) { acc2 += r + 1; r--; }
            const int c = tt - acc2;
            row0 = r * 128; col0 = c * 128;
            pA = g_qh + ((size_t)zb * SEQ + row0) * DIM;
            pB = g_xh + ((size_t)zb * SEQ + col0) * DIM;   // B = x itself!
            ldA = DIM; ldB = DIM;
            nChunks = DIM / KC;
            pubIdx = C_SC + zb * 16 + r;
            if (tid == 0) {
                wait_cnt(C_Q + zb * 16 + r, 8);
                wait_cnt(C_X + zb * 16 + c, 4);
                __threadfence();
            }
            __syncthreads();
        } else {                                            // ---- PV -> out --
            mode = 1;
            const int t = bid - B_PV2;
            zb = t & 3;
            const int u = t >> 2;
            const int r = 15 - (u >> 3);                    // long rows first
            const int xb = u & 7;
            row0 = r * 128; col0 = xb * 128;
            pA = g_ph + (size_t)zb * ((size_t)SEQ * SEQ) + (size_t)row0 * SEQ;
            pB = g_vth + (size_t)zb * ((size_t)DIM * SEQ) + (size_t)col0 * SEQ;
            ldA = SEQ; ldB = SEQ;
            nChunks = ((r + 1) * 128) / KC;
            if (tid == 0) {
                for (int j = 0; j <= r; j++) wait_cnt(C_V + zb * 16 + j, 8);
                wait_cnt(C_SC + zb * 16 + r, r + 1);
                __threadfence();
            }
            __syncthreads();
        }

        // ---------------- Shared mainloop ----------------
        float acc[4][8][4];
        #pragma unroll
        for (int i = 0; i < 4; i++)
            #pragma unroll
            for (int j = 0; j < 8; j++)
                #pragma unroll
                for (int q = 0; q < 4; q++) acc[i][j][q] = 0.0f;

        #pragma unroll
        for (int s = 0; s < NS - 1; s++) {
            if (s < nChunks) {
                const uint32_t st = sb + s * STG_B;
                const int k0 = s * KC;
                load_tile_async(st,          pA + k0, ldA, tid);
                load_tile_async(st + TILE_P, pB + k0, ldB, tid);
            }
            cpa_commit();
        }

        uint32_t ah[2][4][4], bh[2][4][4];

        for (int c = 0; c < nChunks; c++) {
            asm volatile("cp.async.wait_group %0;" :: "n"(NS - 2));
            __syncthreads();

            const uint32_t st = sb + (c % NS) * STG_B;

            #pragma unroll
            for (int mb = 0; mb < 4; mb++)
                ldm_x4(ah[0][mb], st + aoff0 + mb * 16 * (LDT * 2));
            #pragma unroll
            for (int nh = 0; nh < 4; nh++)
                ldm_x4(bh[0][nh], st + TILE_P + boff0 + nh * 16 * (LDT * 2));

            #pragma unroll
            for (int ks = 0; ks < 4; ks++) {
                const int cur = ks & 1;
                if (ks < 3) {
                    const uint32_t kb = (ks + 1) * 32;
                    #pragma unroll
                    for (int mb = 0; mb < 4; mb++)
                        ldm_x4(ah[cur ^ 1][mb],
                               st + aoff0 + mb * 16 * (LDT * 2) + kb);
                    #pragma unroll
                    for (int nh = 0; nh < 4; nh++)
                        ldm_x4(bh[cur ^ 1][nh],
                               st + TILE_P + boff0 + nh * 16 * (LDT * 2) + kb);
                }
                #pragma unroll
                for (int mb = 0; mb < 4; mb++) {
                    #pragma unroll
                    for (int nb = 0; nb < 8; nb++) {
                        const int nh = nb >> 1, p = (nb & 1) * 2;
                        mma16816(acc[mb][nb], ah[cur][mb],
                                 bh[cur][nh][p], bh[cur][nh][p + 1]);
                    }
                }
            }

            const int cn = c + NS - 1;
            if (cn < nChunks) {
                const uint32_t stn = sb + (cn % NS) * STG_B;
                const int k0 = cn * KC;
                load_tile_async(stn,          pA + k0, ldA, tid);
                load_tile_async(stn + TILE_P, pB + k0, ldB, tid);
            }
            cpa_commit();
        }
        asm volatile("cp.async.wait_group 0;");   // drain before smem reuse

        // ---------------- Epilogues ----------------
        if (mode == 2) {
            // scores -> P = exp(scale*s) masked, fp16 + row-sum atomics
            #pragma unroll
            for (int mb = 0; mb < 4; mb++) {
                const int m0 = row0 + warp_m * 64 + mb * 16 + gq;
                const int m1 = m0 + 8;
                float sum0 = 0.0f, sum1 = 0.0f;
                #pragma unroll
                for (int nb = 0; nb < 8; nb++) {
                    const int n = col0 + warp_n * 64 + nb * 8 + tq * 2;
                    const float* cc = acc[mb][nb];
                    float p00 = (n     <= m0) ? __expf(cc[0] * SM_SCALE) : 0.0f;
                    float p01 = (n + 1 <= m0) ? __expf(cc[1] * SM_SCALE) : 0.0f;
                    float p10 = (n     <= m1) ? __expf(cc[2] * SM_SCALE) : 0.0f;
                    float p11 = (n + 1 <= m1) ? __expf(cc[3] * SM_SCALE) : 0.0f;
                    sum0 += p00 + p01;
                    sum1 += p10 + p11;
                    size_t o0 = (size_t)zb * SEQ * SEQ + (size_t)m0 * SEQ + n;
                    size_t o1 = (size_t)zb * SEQ * SEQ + (size_t)m1 * SEQ + n;
                    *reinterpret_cast<uint32_t*>(g_ph + o0) = pack2h(p00, p01);
                    *reinterpret_cast<uint32_t*>(g_ph + o1) = pack2h(p10, p11);
                }
                #pragma unroll
                for (int o = 1; o < 4; o <<= 1) {
                    sum0 += __shfl_xor_sync(0xffffffffu, sum0, o);
                    sum1 += __shfl_xor_sync(0xffffffffu, sum1, o);
                }
                if (tq == 0) {
                    atomicAdd(&g_rsum[(size_t)zb * SEQ + m0], sum0);
                    atomicAdd(&g_rsum[(size_t)zb * SEQ + m1], sum1);
                }
            }
        } else if (mode == 1) {
            // PV -> out = acc / rsum, fp32 (FINAL)
            #pragma unroll
            for (int mb = 0; mb < 4; mb++) {
                const int m = row0 + warp_m * 64 + mb * 16 + gq;
                const float inv0 = 1.0f / g_rsum[(size_t)zb * SEQ + m];
                const float inv1 = 1.0f / g_rsum[(size_t)zb * SEQ + m + 8];
                #pragma unroll
                for (int nb = 0; nb < 8; nb++) {
                    const int n = col0 + warp_n * 64 + nb * 8 + tq * 2;
                    const float* cc = acc[mb][nb];
                    float* d0 = out + ((size_t)zb * SEQ + m) * DIM + n;
                    float* d1 = out + ((size_t)zb * SEQ + m + 8) * DIM + n;
                    *reinterpret_cast<float2*>(d0) =
                        make_float2(cc[0] * inv0, cc[1] * inv0);
                    *reinterpret_cast<float2*>(d1) =
                        make_float2(cc[2] * inv1, cc[3] * inv1);
                }
            }
        } else if (mode == 5 || mode == 4) {
            // Wqk^T / Wvo^T fp16 out
            __half* dst = (mode == 5) ? g_wqkth : g_wvoth;
            #pragma unroll
            for (int mb = 0; mb < 4; mb++) {
                const int m = row0 + warp_m * 64 + mb * 16 + gq;
                #pragma unroll
                for (int nb = 0; nb < 8; nb++) {
                    const int n = col0 + warp_n * 64 + nb * 8 + tq * 2;
                    const float* cc = acc[mb][nb];
                    size_t o0 = (size_t)m * DIM + n;
                    size_t o1 = (size_t)(m + 8) * DIM + n;
                    *reinterpret_cast<uint32_t*>(dst + o0) = pack2h(cc[0], cc[1]);
                    *reinterpret_cast<uint32_t*>(dst + o1) = pack2h(cc[2], cc[3]);
                }
            }
        } else if (col0 < 1024) {
            // proj, Q' region -> fp16 [8192][1024]
            #pragma unroll
            for (int mb = 0; mb < 4; mb++) {
                const int m = row0 + warp_m * 64 + mb * 16 + gq;
                #pragma unroll
                for (int nb = 0; nb < 8; nb++) {
                    const int n = col0 + warp_n * 64 + nb * 8 + tq * 2;
                    const float* cc = acc[mb][nb];
                    size_t o0 = (size_t)m * DIM + n;
                    size_t o1 = (size_t)(m + 8) * DIM + n;
                    *reinterpret_cast<uint32_t*>(g_qh + o0) = pack2h(cc[0], cc[1]);
                    *reinterpret_cast<uint32_t*>(g_qh + o1) = pack2h(cc[2], cc[3]);
                }
            }
        } else {
            // proj, V' region: transpose through smem, write fp16 V'^T
            float* smt = reinterpret_cast<float*>(smem);   // [128][129]
            __syncthreads();
            #pragma unroll
            for (int mb = 0; mb < 4; mb++) {
                const int m = warp_m * 64 + mb * 16 + gq;
                #pragma unroll
                for (int nb = 0; nb < 8; nb++) {
                    const int n = warp_n * 64 + nb * 8 + tq * 2;
                    const float* cc = acc[mb][nb];
                    smt[m * 129 + n]           = cc[0];
                    smt[m * 129 + n + 1]       = cc[1];
                    smt[(m + 8) * 129 + n]     = cc[2];
                    smt[(m + 8) * 129 + n + 1] = cc[3];
                }
            }
            __syncthreads();
            const int b  = row0 >> 11;
            const int s0 = row0 & (SEQ - 1);
            const int nl = tid;
            const size_t base = (size_t)b * DIM * SEQ +
                                (size_t)(col0 - 1024 + nl) * SEQ + s0;
            #pragma unroll
            for (int u = 0; u < 128; u += 2) {
                *reinterpret_cast<uint32_t*>(g_vth + base + u) =
                    pack2h(smt[u * 129 + nl], smt[(u + 1) * 129 + nl]);
            }
        }

        // ---------------- Publish + end-of-item barrier ----------------
        __syncthreads();
        if (tid == 0 && pubIdx >= 0) publish(pubIdx);
    }
}

// ---------------------------------------------------------------------------
// Launch
// ---------------------------------------------------------------------------
extern "C" void kernel_launch(void* const* d_in, const int* in_sizes, int n_in,
                              void* d_out, int out_size)
{
    const float* x  = (const float*)d_in[0];
    const float* Wq = (const float*)d_in[1];
    const float* Wk = (const float*)d_in[2];
    const float* Wv = (const float*)d_in[3];
    const float* Wo = (const float*)d_in[4];
    float* out = (float*)d_out;

    cudaFuncSetAttribute(mega, cudaFuncAttributeMaxDynamicSharedMemorySize, SMEM_B);

    float* rsum;
    int* cnt;
    cudaGetSymbolAddress((void**)&rsum, g_rsum);
    cudaGetSymbolAddress((void**)&cnt, g_cnt);

    cudaMemsetAsync(cnt, 0, N_CNT * sizeof(int));
    cudaMemsetAsync(rsum, 0, (size_t)BATCH * SEQ * sizeof(float));

    mega<<<NWORKERS, GT, SMEM_B>>>(x, Wq, Wk, Wv, Wo, out);
}

// round 17
// speedup vs baseline: 1.2776x; 1.0310x over previous
#include <cuda_runtime.h>
#include <cuda_fp16.h>
#include <cstdint>
#include <cstddef>

// ---------------------------------------------------------------------------
// Problem constants
// ---------------------------------------------------------------------------
#define BATCH 4
#define SEQ   2048
#define DIM   1024

// GEMM tiling: 128x128 CTA tile, 4 warps of 64x64, K chunks of 64 fp16.
#define KC     64
#define LDT    72                       // padded row stride in fp16 (144 B)
#define TILE_P (128 * LDT * 2)          // 18432 B per tile
#define STG_B  (2 * TILE_P)             // 36864 B (A + B)
#define NS     3                        // pipeline stages
#define SMEM_B (NS * STG_B)             // 110592 B -> 2 CTAs/SM
#define GT     128                      // threads per CTA (4 warps)

#define SM_SCALE 0.03125f               // 1/sqrt(1024)

// Work-queue (topological order, critical-path-aware):
//   W converts | Wo^T | Wqk^T GEMM | Wvo^T GEMM | x conv | proj | scores | PV
#define B_WN    0
#define N_WN    96
#define B_WOT   96                      // Wo transpose tiles
#define B_WQK   352                     // Wqk^T = Wk x Wq^T, 8x8 tiles
#define B_WVO   416                     // Wvo^T = Wo^T x Wv, 8x8 tiles
#define B_PX    480                     // x -> fp16
#define B_PROJ  736                     // Q'|V' = x @ [Wqk|Wvo], 16 x 64
#define B_SC2   1760                    // scores, 136 x 4
#define B_PV2   2304                    // PV, 512
#define N_ALL   2816

#define NWORKERS 304

// Counter layout
#define C_X    0                        // [0:64)    x blocks, target 4
#define C_WQN  64                       // Wq fp16 blocks, target 4
#define C_WKN  72                       // Wk fp16 blocks, target 4
#define C_WVN  80                       // Wv fp16 blocks, target 4
#define C_WOT  88                       // Wo^T row-blocks, target 32
#define C_WQK  96                       // Wqk^T row-blocks, target 8
#define C_WVO  104                      // Wvo^T row-blocks, target 8
#define C_Q    112                      // Q' row-blocks, target 8
#define C_V    176                      // V' row-blocks, target 8
#define C_SC   240                      // scores rows, target r+1
#define Q_HEAD 320
#define N_CNT  512

// ---------------------------------------------------------------------------
// PTX helpers (base sm_103 ISA: cp.async, ldmatrix, mma.sync)
// ---------------------------------------------------------------------------
__device__ __forceinline__ uint32_t smem_u32(const void* p) {
    uint32_t a;
    asm("{ .reg .u64 t; cvta.to.shared.u64 t, %1; cvt.u32.u64 %0, t; }"
        : "=r"(a) : "l"(p));
    return a;
}
__device__ __forceinline__ void cpa16(uint32_t dst, const void* src) {
    asm volatile("cp.async.cg.shared.global [%0], [%1], 16;"
                 :: "r"(dst), "l"(src));
}
__device__ __forceinline__ void cpa_commit() {
    asm volatile("cp.async.commit_group;");
}
__device__ __forceinline__ void ldm_x4(uint32_t* r, uint32_t addr) {
    asm volatile("ldmatrix.sync.aligned.m8n8.x4.shared.b16 {%0,%1,%2,%3}, [%4];"
                 : "=r"(r[0]), "=r"(r[1]), "=r"(r[2]), "=r"(r[3]) : "r"(addr));
}
__device__ __forceinline__ void mma16816(float* d, const uint32_t* a,
                                         uint32_t b0, uint32_t b1) {
    asm volatile(
        "mma.sync.aligned.m16n8k16.row.col.f32.f16.f16.f32 "
        "{%0,%1,%2,%3}, {%4,%5,%6,%7}, {%8,%9}, {%0,%1,%2,%3};"
        : "+f"(d[0]), "+f"(d[1]), "+f"(d[2]), "+f"(d[3])
        : "r"(a[0]), "r"(a[1]), "r"(a[2]), "r"(a[3]), "r"(b0), "r"(b1));
}
__device__ __forceinline__ uint32_t pack2h(float a, float b) {
    __half ha = __float2half_rn(a), hb = __float2half_rn(b);
    return (uint32_t)__half_as_ushort(ha) | ((uint32_t)__half_as_ushort(hb) << 16);
}

// ---------------------------------------------------------------------------
// Device scratch + dependency counters
// ---------------------------------------------------------------------------
#define RXD ((size_t)BATCH * SEQ * DIM)
#define RSS ((size_t)BATCH * SEQ * SEQ)
__device__ __half g_xh[RXD];                 // x fp16 (A of proj, B of scores)
__device__ __half g_wqh[DIM * DIM];          // Wq fp16 natural
__device__ __half g_wkh[DIM * DIM];          // Wk fp16 natural
__device__ __half g_wvh[DIM * DIM];          // Wv fp16 natural
__device__ __half g_woth[DIM * DIM];         // Wo^T fp16
__device__ __half g_wqkth[DIM * DIM];        // (Wq@Wk^T)^T fp16
__device__ __half g_wvoth[DIM * DIM];        // (Wv@Wo)^T fp16
__device__ __half g_qh[RXD];                 // Q' fp16 [8192][1024]
__device__ __half g_vth[RXD];                // V'^T fp16 [B][DV][SEQ]
__device__ __half g_ph[RSS];                 // P = exp(s*scale) fp16
__device__ float  g_rsum[(size_t)BATCH * SEQ];
__device__ int    g_cnt[N_CNT];

__device__ __forceinline__ void wait_cnt(int idx, int target) {
    volatile int* p = &g_cnt[idx];
    while (*p < target) __nanosleep(64);
}
__device__ __forceinline__ void publish(int idx) {
    __threadfence();
    atomicAdd(&g_cnt[idx], 1);
}

// ---------------------------------------------------------------------------
// Async tile load: 128 rows x 64 fp16 (K-major) -> padded smem (stride LDT)
// ---------------------------------------------------------------------------
__device__ __forceinline__ void load_tile_async(uint32_t base,
                                                const __half* __restrict__ gp,
                                                int ld, int tid) {
    #pragma unroll
    for (int i = 0; i < 8; i++) {
        int idx = i * GT + tid;           // 0..1023
        int row = idx >> 3;
        int c16 = idx & 7;
        cpa16(base + row * (LDT * 2) + c16 * 16,
              gp + (size_t)row * ld + c16 * 8);
    }
}

// fp32 -> fp16 block convert: 32 rows of DIM floats
__device__ __forceinline__ void conv_rows(const float* __restrict__ src,
                                          __half* __restrict__ dst, int tid) {
    #pragma unroll 8
    for (int i = 0; i < 64; i++) {
        const int idx = i * GT + tid;     // 8192 float4
        float4 v = reinterpret_cast<const float4*>(src)[idx];
        uint2 o;
        o.x = pack2h(v.x, v.y);
        o.y = pack2h(v.z, v.w);
        reinterpret_cast<uint2*>(dst)[idx] = o;
    }
}

// ---------------------------------------------------------------------------
// Persistent megakernel, ordered atomic work queue (deadlock-free).
// ---------------------------------------------------------------------------
__global__ __launch_bounds__(GT, 2)
void mega(const float* __restrict__ x,
          const float* __restrict__ Wq, const float* __restrict__ Wk,
          const float* __restrict__ Wv, const float* __restrict__ Wo,
          float* __restrict__ out)
{
    const int tid  = threadIdx.x;
    extern __shared__ char smem[];
    __shared__ int s_item;

    const int wid  = tid >> 5;
    const int lane = tid & 31;
    const int warp_m = wid >> 1;
    const int warp_n = wid & 1;
    const int gq = lane >> 2;
    const int tq = lane & 3;

    const int a_r  = lane & 15;
    const int a_kq = (lane >> 4) << 3;
    const int b_r  = (lane & 7) + ((lane >= 16) ? 8 : 0);
    const int b_kq = ((lane >> 3) & 1) << 3;
    const uint32_t sb = smem_u32(smem);
    const uint32_t aoff0 = (warp_m * 64 + a_r) * (LDT * 2) + a_kq * 2;
    const uint32_t boff0 = (warp_n * 64 + b_r) * (LDT * 2) + b_kq * 2;

    for (;;) {
        if (tid == 0) s_item = atomicAdd(&g_cnt[Q_HEAD], 1);
        __syncthreads();
        const int bid = s_item;
        if (bid >= N_ALL) return;

        // ============ Prep: Wq, Wk, Wv natural converts ============
        if (bid < B_WOT) {
            const int w = bid - B_WN;         // 0..95
            const int z = w >> 5;             // 0=Wq 1=Wk 2=Wv
            const int r32 = w & 31;
            const float* in = (z == 0) ? Wq : (z == 1) ? Wk : Wv;
            __half* dh = (z == 0) ? g_wqh : (z == 1) ? g_wkh : g_wvh;
            const size_t base = (size_t)r32 * 32 * DIM;
            conv_rows(in + base, dh + base, tid);
            __syncthreads();
            if (tid == 0) publish(((z == 0) ? C_WQN : (z == 1) ? C_WKN : C_WVN)
                                  + (r32 >> 2));
            continue;
        }
        // ============ Prep: Wo transpose ============
        if (bid < B_WQK) {
            const int t = bid - B_WOT;        // 0..255
            const int tx = t & 15, ty = t >> 4;
            float* tile = reinterpret_cast<float*>(smem);   // [64][65]
            const int bx = tx * 64, by = ty * 64;
            #pragma unroll
            for (int i = 0; i < 32; i++) {
                const int e = i * GT + tid;
                const int r = e >> 6, c = e & 63;
                tile[r * 65 + c] = Wo[(size_t)(by + r) * DIM + bx + c];
            }
            __syncthreads();
            #pragma unroll
            for (int i = 0; i < 32; i++) {
                const int e = i * GT + tid;
                const int r = e >> 6, c = e & 63;
                g_woth[(size_t)(bx + r) * DIM + by + c] =
                    __float2half_rn(tile[c * 65 + r]);
            }
            __syncthreads();
            if (tid == 0) publish(C_WOT + (tx >> 1));
            continue;
        }
        // ============ Prep: x fp32 -> fp16 (after weight GEMMs in queue) ====
        if (bid >= B_PX && bid < B_PROJ) {
            const int t = bid - B_PX;
            const int rb = t >> 2;
            const int q  = t & 3;
            const size_t base = ((size_t)rb * 128 + q * 32) * DIM;
            conv_rows(x + base, g_xh + base, tid);
            __syncthreads();
            if (tid == 0) publish(C_X + rb);
            continue;
        }

        // ============ GEMM items ============
        // mode: 5 = Wqk^T out, 4 = Wvo^T out, 3 = proj (Q'|V'), 2 = scores,
        //       1 = PV -> out
        int mode, row0, col0, zb = 0, nChunks, pubIdx = -1;
        const __half* pA;
        const __half* pB;
        int ldA, ldB;

        if (bid < B_WVO) {                                  // ---- Wqk^T ----
            // Wqk^T[n][k] = sum_j Wk[n][j]*Wq[k][j]; A=Wk, B=Wq (natural)
            mode = 5;
            const int t = bid - B_WQK;
            const int rw = t >> 3, cb = t & 7;
            row0 = rw * 128; col0 = cb * 128;
            pA = g_wkh + (size_t)row0 * DIM;
            pB = g_wqh + (size_t)col0 * DIM;
            ldA = DIM; ldB = DIM;
            nChunks = DIM / KC;
            pubIdx = C_WQK + rw;
            if (tid == 0) {
                wait_cnt(C_WKN + rw, 4);
                wait_cnt(C_WQN + cb, 4);
                __threadfence();
            }
            __syncthreads();
        } else if (bid < B_PX) {                            // ---- Wvo^T ----
            mode = 4;
            const int t = bid - B_WVO;
            const int rw = t >> 3, cb = t & 7;
            row0 = rw * 128; col0 = cb * 128;
            pA = g_woth + (size_t)row0 * DIM;
            pB = g_wvh + (size_t)col0 * DIM;
            ldA = DIM; ldB = DIM;
            nChunks = DIM / KC;
            pubIdx = C_WVO + rw;
            if (tid == 0) {
                wait_cnt(C_WOT + rw, 32);
                wait_cnt(C_WVN + cb, 4);
                __threadfence();
            }
            __syncthreads();
        } else if (bid < B_SC2) {                           // ---- proj ----
            mode = 3;
            const int t = bid - B_PROJ;
            const int xb = t & 15, u = t >> 4;              // u 0..63
            // Q' (xb<8): rows DESCENDING per batch (scores r=15 chain first)
            // V' (xb>=8): rows ASCENDING per batch (low-r PV unblocks early)
            // batches interleaved so rows complete together across zb.
            const int zbq = u & 3;
            const int rr  = u >> 2;                         // 0..15
            const int y = (xb < 8) ? (zbq * 16 + (15 - rr))
                                   : (zbq * 16 + rr);
            row0 = y * 128; col0 = xb * 128;
            pA = g_xh + (size_t)row0 * DIM;
            ldA = DIM; ldB = DIM;
            nChunks = DIM / KC;
            if (xb < 8) {
                pB = g_wqkth + (size_t)col0 * DIM;
                pubIdx = C_Q + y;
            } else {
                pB = g_wvoth + (size_t)(xb - 8) * 128 * DIM;
                pubIdx = C_V + y;
            }
            if (tid == 0) {
                wait_cnt(C_X + y, 4);
                if (xb < 8) wait_cnt(C_WQK + xb, 8);
                else        wait_cnt(C_WVO + (xb - 8), 8);
                __threadfence();
            }
            __syncthreads();
        } else if (bid < B_PV2) {                           // ---- scores ----
            mode = 2;
            const int t = bid - B_SC2;
            zb = t & 3;
            int tt = t >> 2;                                // r descending
            int r = 15, acc2 = 0;
            while (tt >= acc2 + (r + 1)) { acc2 += r + 1; r--; }
            const int c = tt - acc2;
            row0 = r * 128; col0 = c * 128;
            pA = g_qh + ((size_t)zb * SEQ + row0) * DIM;
            pB = g_xh + ((size_t)zb * SEQ + col0) * DIM;   // B = x itself
            ldA = DIM; ldB = DIM;
            nChunks = DIM / KC;
            pubIdx = C_SC + zb * 16 + r;
            if (tid == 0) {
                wait_cnt(C_Q + zb * 16 + r, 8);
                wait_cnt(C_X + zb * 16 + c, 4);
                __threadfence();
            }
            __syncthreads();
        } else {                                            // ---- PV -> out --
            mode = 1;
            const int t = bid - B_PV2;
            zb = t & 3;
            const int u = t >> 2;
            const int r = 15 - (u >> 3);                    // long rows first
            const int xb = u & 7;
            row0 = r * 128; col0 = xb * 128;
            pA = g_ph + (size_t)zb * ((size_t)SEQ * SEQ) + (size_t)row0 * SEQ;
            pB = g_vth + (size_t)zb * ((size_t)DIM * SEQ) + (size_t)col0 * SEQ;
            ldA = SEQ; ldB = SEQ;
            nChunks = ((r + 1) * 128) / KC;
            if (tid == 0) {
                for (int j = 0; j <= r; j++) wait_cnt(C_V + zb * 16 + j, 8);
                wait_cnt(C_SC + zb * 16 + r, r + 1);
                __threadfence();
            }
            __syncthreads();
        }

        // ---------------- Shared mainloop ----------------
        float acc[4][8][4];
        #pragma unroll
        for (int i = 0; i < 4; i++)
            #pragma unroll
            for (int j = 0; j < 8; j++)
                #pragma unroll
                for (int q = 0; q < 4; q++) acc[i][j][q] = 0.0f;

        #pragma unroll
        for (int s = 0; s < NS - 1; s++) {
            if (s < nChunks) {
                const uint32_t st = sb + s * STG_B;
                const int k0 = s * KC;
                load_tile_async(st,          pA + k0, ldA, tid);
                load_tile_async(st + TILE_P, pB + k0, ldB, tid);
            }
            cpa_commit();
        }

        uint32_t ah[2][4][4], bh[2][4][4];

        for (int c = 0; c < nChunks; c++) {
            asm volatile("cp.async.wait_group %0;" :: "n"(NS - 2));
            __syncthreads();

            const uint32_t st = sb + (c % NS) * STG_B;

            #pragma unroll
            for (int mb = 0; mb < 4; mb++)
                ldm_x4(ah[0][mb], st + aoff0 + mb * 16 * (LDT * 2));
            #pragma unroll
            for (int nh = 0; nh < 4; nh++)
                ldm_x4(bh[0][nh], st + TILE_P + boff0 + nh * 16 * (LDT * 2));

            #pragma unroll
            for (int ks = 0; ks < 4; ks++) {
                const int cur = ks & 1;
                if (ks < 3) {
                    const uint32_t kb = (ks + 1) * 32;
                    #pragma unroll
                    for (int mb = 0; mb < 4; mb++)
                        ldm_x4(ah[cur ^ 1][mb],
                               st + aoff0 + mb * 16 * (LDT * 2) + kb);
                    #pragma unroll
                    for (int nh = 0; nh < 4; nh++)
                        ldm_x4(bh[cur ^ 1][nh],
                               st + TILE_P + boff0 + nh * 16 * (LDT * 2) + kb);
                }
                #pragma unroll
                for (int mb = 0; mb < 4; mb++) {
                    #pragma unroll
                    for (int nb = 0; nb < 8; nb++) {
                        const int nh = nb >> 1, p = (nb & 1) * 2;
                        mma16816(acc[mb][nb], ah[cur][mb],
                                 bh[cur][nh][p], bh[cur][nh][p + 1]);
                    }
                }
            }

            const int cn = c + NS - 1;
            if (cn < nChunks) {
                const uint32_t stn = sb + (cn % NS) * STG_B;
                const int k0 = cn * KC;
                load_tile_async(stn,          pA + k0, ldA, tid);
                load_tile_async(stn + TILE_P, pB + k0, ldB, tid);
            }
            cpa_commit();
        }
        asm volatile("cp.async.wait_group 0;");   // drain before smem reuse

        // ---------------- Epilogues ----------------
        if (mode == 2) {
            // scores -> P = exp(scale*s) masked, fp16 + row-sum atomics
            #pragma unroll
            for (int mb = 0; mb < 4; mb++) {
                const int m0 = row0 + warp_m * 64 + mb * 16 + gq;
                const int m1 = m0 + 8;
                float sum0 = 0.0f, sum1 = 0.0f;
                #pragma unroll
                for (int nb = 0; nb < 8; nb++) {
                    const int n = col0 + warp_n * 64 + nb * 8 + tq * 2;
                    const float* cc = acc[mb][nb];
                    float p00 = (n     <= m0) ? __expf(cc[0] * SM_SCALE) : 0.0f;
                    float p01 = (n + 1 <= m0) ? __expf(cc[1] * SM_SCALE) : 0.0f;
                    float p10 = (n     <= m1) ? __expf(cc[2] * SM_SCALE) : 0.0f;
                    float p11 = (n + 1 <= m1) ? __expf(cc[3] * SM_SCALE) : 0.0f;
                    sum0 += p00 + p01;
                    sum1 += p10 + p11;
                    size_t o0 = (size_t)zb * SEQ * SEQ + (size_t)m0 * SEQ + n;
                    size_t o1 = (size_t)zb * SEQ * SEQ + (size_t)m1 * SEQ + n;
                    *reinterpret_cast<uint32_t*>(g_ph + o0) = pack2h(p00, p01);
                    *reinterpret_cast<uint32_t*>(g_ph + o1) = pack2h(p10, p11);
                }
                #pragma unroll
                for (int o = 1; o < 4; o <<= 1) {
                    sum0 += __shfl_xor_sync(0xffffffffu, sum0, o);
                    sum1 += __shfl_xor_sync(0xffffffffu, sum1, o);
                }
                if (tq == 0) {
                    atomicAdd(&g_rsum[(size_t)zb * SEQ + m0], sum0);
                    atomicAdd(&g_rsum[(size_t)zb * SEQ + m1], sum1);
                }
            }
        } else if (mode == 1) {
            // PV -> out = acc / rsum, fp32 (FINAL)
            #pragma unroll
            for (int mb = 0; mb < 4; mb++) {
                const int m = row0 + warp_m * 64 + mb * 16 + gq;
                const float inv0 = 1.0f / g_rsum[(size_t)zb * SEQ + m];
                const float inv1 = 1.0f / g_rsum[(size_t)zb * SEQ + m + 8];
                #pragma unroll
                for (int nb = 0; nb < 8; nb++) {
                    const int n = col0 + warp_n * 64 + nb * 8 + tq * 2;
                    const float* cc = acc[mb][nb];
                    float* d0 = out + ((size_t)zb * SEQ + m) * DIM + n;
                    float* d1 = out + ((size_t)zb * SEQ + m + 8) * DIM + n;
                    *reinterpret_cast<float2*>(d0) =
                        make_float2(cc[0] * inv0, cc[1] * inv0);
                    *reinterpret_cast<float2*>(d1) =
                        make_float2(cc[2] * inv1, cc[3] * inv1);
                }
            }
        } else if (mode == 5 || mode == 4) {
            // Wqk^T / Wvo^T fp16 out
            __half* dst = (mode == 5) ? g_wqkth : g_wvoth;
            #pragma unroll
            for (int mb = 0; mb < 4; mb++) {
                const int m = row0 + warp_m * 64 + mb * 16 + gq;
                #pragma unroll
                for (int nb = 0; nb < 8; nb++) {
                    const int n = col0 + warp_n * 64 + nb * 8 + tq * 2;
                    const float* cc = acc[mb][nb];
                    size_t o0 = (size_t)m * DIM + n;
                    size_t o1 = (size_t)(m + 8) * DIM + n;
                    *reinterpret_cast<uint32_t*>(dst + o0) = pack2h(cc[0], cc[1]);
                    *reinterpret_cast<uint32_t*>(dst + o1) = pack2h(cc[2], cc[3]);
                }
            }
        } else if (col0 < 1024) {
            // proj, Q' region -> fp16 [8192][1024]
            #pragma unroll
            for (int mb = 0; mb < 4; mb++) {
                const int m = row0 + warp_m * 64 + mb * 16 + gq;
                #pragma unroll
                for (int nb = 0; nb < 8; nb++) {
                    const int n = col0 + warp_n * 64 + nb * 8 + tq * 2;
                    const float* cc = acc[mb][nb];
                    size_t o0 = (size_t)m * DIM + n;
                    size_t o1 = (size_t)(m + 8) * DIM + n;
                    *reinterpret_cast<uint32_t*>(g_qh + o0) = pack2h(cc[0], cc[1]);
                    *reinterpret_cast<uint32_t*>(g_qh + o1) = pack2h(cc[2], cc[3]);
                }
            }
        } else {
            // proj, V' region: transpose through smem, write fp16 V'^T
            float* smt = reinterpret_cast<float*>(smem);   // [128][129]
            __syncthreads();
            #pragma unroll
            for (int mb = 0; mb < 4; mb++) {
                const int m = warp_m * 64 + mb * 16 + gq;
                #pragma unroll
                for (int nb = 0; nb < 8; nb++) {
                    const int n = warp_n * 64 + nb * 8 + tq * 2;
                    const float* cc = acc[mb][nb];
                    smt[m * 129 + n]           = cc[0];
                    smt[m * 129 + n + 1]       = cc[1];
                    smt[(m + 8) * 129 + n]     = cc[2];
                    smt[(m + 8) * 129 + n + 1] = cc[3];
                }
            }
            __syncthreads();
            const int b  = row0 >> 11;
            const int s0 = row0 & (SEQ - 1);
            const int nl = tid;
            const size_t base = (size_t)b * DIM * SEQ +
                                (size_t)(col0 - 1024 + nl) * SEQ + s0;
            #pragma unroll
            for (int u = 0; u < 128; u += 2) {
                *reinterpret_cast<uint32_t*>(g_vth + base + u) =
                    pack2h(smt[u * 129 + nl], smt[(u + 1) * 129 + nl]);
            }
        }

        // ---------------- Publish + end-of-item barrier ----------------
        __syncthreads();
        if (tid == 0 && pubIdx >= 0) publish(pubIdx);
    }
}

// ---------------------------------------------------------------------------
// Launch
// ---------------------------------------------------------------------------
extern "C" void kernel_launch(void* const* d_in, const int* in_sizes, int n_in,
                              void* d_out, int out_size)
{
    const float* x  = (const float*)d_in[0];
    const float* Wq = (const float*)d_in[1];
    const float* Wk = (const float*)d_in[2];
    const float* Wv = (const float*)d_in[3];
    const float* Wo = (const float*)d_in[4];
    float* out = (float*)d_out;

    cudaFuncSetAttribute(mega, cudaFuncAttributeMaxDynamicSharedMemorySize, SMEM_B);

    float* rsum;
    int* cnt;
    cudaGetSymbolAddress((void**)&rsum, g_rsum);
    cudaGetSymbolAddress((void**)&cnt, g_cnt);

    cudaMemsetAsync(cnt, 0, N_CNT * sizeof(int));
    cudaMemsetAsync(rsum, 0, (size_t)BATCH * SEQ * sizeof(float));

    mega<<<NWORKERS, GT, SMEM_B>>>(x, Wq, Wk, Wv, Wo, out);
}